// round 2
// baseline (speedup 1.0000x reference)
#include <cuda_runtime.h>
#include <math.h>

#define Nn 2048
#define Cc 1024
#define Hh 8
#define Dd 128
#define SCALE_F 25.0f

// ---------------- scratch (static device globals; no allocs) ----------------
__device__ __align__(128) float g_qkv_cls[Nn * 3 * Cc];     // [N,3,H,d]
__device__ __align__(128) float g_qkv_reg[Nn * 3 * Cc];
__device__ __align__(128) float g_qn[2 * Hh * Nn * Dd];     // normalized q, [set][H][N][d]
__device__ __align__(128) float g_kn[2 * Hh * Nn * Dd];     // normalized*SCALE*score k
__device__ __align__(128) float g_v[Hh * Nn * Dd];          // raw v_cls, [H][N][d]
__device__ __align__(128) float g_vn[Nn * Cc];              // per-head-normalized v, [N, H*d]
__device__ __align__(128) float g_S0[Hh * Nn * Nn];         // cls scores -> attn probs
__device__ __align__(128) float g_S1[Hh * Nn * Nn];         // reg scores
__device__ __align__(128) float g_simraw[Nn * Nn];          // sum_h vn.vn
__device__ __align__(128) float g_attnsum[Nn * Nn];         // sum_h attn
__device__ __align__(128) float g_x[Nn * 2 * Cc];           // trans_cls = [x | x_ori]
__device__ __align__(128) float g_sim2[Nn * Nn];            // sim_round2
__device__ __align__(128) float g_ave[Nn * 4 * Cc];         // [soft_sim | feat]

// ---------------- reductions ----------------
__device__ __forceinline__ float warpMax(float v) {
#pragma unroll
    for (int o = 16; o; o >>= 1) v = fmaxf(v, __shfl_xor_sync(0xffffffffu, v, o));
    return v;
}
__device__ __forceinline__ float warpSum(float v) {
#pragma unroll
    for (int o = 16; o; o >>= 1) v += __shfl_xor_sync(0xffffffffu, v, o);
    return v;
}
// blockDim.x == 256 (8 warps)
__device__ float blockMax(float v, float* s) {
    int w = threadIdx.x >> 5, l = threadIdx.x & 31;
    v = warpMax(v);
    if (l == 0) s[w] = v;
    __syncthreads();
    float r = (l < 8) ? s[l] : -3.0e38f;
    r = warpMax(r);
    r = __shfl_sync(0xffffffffu, r, 0);
    __syncthreads();
    return r;
}
__device__ float blockSum(float v, float* s) {
    int w = threadIdx.x >> 5, l = threadIdx.x & 31;
    v = warpSum(v);
    if (l == 0) s[w] = v;
    __syncthreads();
    float r = (l < 8) ? s[l] : 0.0f;
    r = warpSum(r);
    r = __shfl_sync(0xffffffffu, r, 0);
    __syncthreads();
    return r;
}

// ---------------- SGEMM: C = A @ op(B) (+bias) ----------------
// TRANSB=true : B is [N,K] row-major (ldb)  -> C = A*B^T
// TRANSB=false: B is [K,N] row-major (ldb)  -> C = A*B
// Requires M%128==0, N%128==0, K%8==0, lda/ldb%4==0, 16B-aligned bases.
template <bool TRANSB>
__global__ void __launch_bounds__(256) gemm_f32(
    const float* __restrict__ A, const float* __restrict__ B, float* __restrict__ C,
    const float* __restrict__ bias,
    int M, int N, int K, int lda, int ldb, int ldc,
    long long sA, long long sB, long long sC)
{
    __shared__ __align__(16) float As[2][8][128];
    __shared__ __align__(16) float Bs[2][8][128];

    A += (long long)blockIdx.z * sA;
    B += (long long)blockIdx.z * sB;
    C += (long long)blockIdx.z * sC;

    const int m0 = blockIdx.y * 128;
    const int n0 = blockIdx.x * 128;
    const int t  = threadIdx.x;
    const int tx = t & 15, ty = t >> 4;

    // A-tile loader (also B when TRANSB): 128 rows x 8 k, float4 along k
    const int arow = t >> 1;
    const int acol = (t & 1) * 4;
    // B-tile loader for NN: 8 k-rows x 128 cols, float4 along n
    const int bk = t >> 5;
    const int bn = (t & 31) * 4;

    float acc[8][8];
#pragma unroll
    for (int i = 0; i < 8; i++)
#pragma unroll
        for (int j = 0; j < 8; j++) acc[i][j] = 0.0f;

    const int ntiles = K >> 3;

    // prologue: tile 0
    float4 a4 = *(const float4*)(A + (long long)(m0 + arow) * lda + acol);
    float4 b4;
    if (TRANSB) b4 = *(const float4*)(B + (long long)(n0 + arow) * ldb + acol);
    else        b4 = *(const float4*)(B + (long long)bk * ldb + n0 + bn);

    As[0][acol + 0][arow] = a4.x;
    As[0][acol + 1][arow] = a4.y;
    As[0][acol + 2][arow] = a4.z;
    As[0][acol + 3][arow] = a4.w;
    if (TRANSB) {
        Bs[0][acol + 0][arow] = b4.x;
        Bs[0][acol + 1][arow] = b4.y;
        Bs[0][acol + 2][arow] = b4.z;
        Bs[0][acol + 3][arow] = b4.w;
    } else {
        *(float4*)&Bs[0][bk][bn] = b4;
    }
    __syncthreads();

    int buf = 0;
    for (int tile = 0; tile < ntiles; ++tile) {
        float4 a4n, b4n;
        const bool more = (tile + 1 < ntiles);
        if (more) {
            const int k0 = (tile + 1) << 3;
            a4n = *(const float4*)(A + (long long)(m0 + arow) * lda + k0 + acol);
            if (TRANSB) b4n = *(const float4*)(B + (long long)(n0 + arow) * ldb + k0 + acol);
            else        b4n = *(const float4*)(B + (long long)(k0 + bk) * ldb + n0 + bn);
        }

#pragma unroll
        for (int kk = 0; kk < 8; kk++) {
            float ar[8], br[8];
            *(float4*)&ar[0] = *(const float4*)&As[buf][kk][ty * 8];
            *(float4*)&ar[4] = *(const float4*)&As[buf][kk][ty * 8 + 4];
            *(float4*)&br[0] = *(const float4*)&Bs[buf][kk][tx * 8];
            *(float4*)&br[4] = *(const float4*)&Bs[buf][kk][tx * 8 + 4];
#pragma unroll
            for (int i = 0; i < 8; i++)
#pragma unroll
                for (int j = 0; j < 8; j++) acc[i][j] = fmaf(ar[i], br[j], acc[i][j]);
        }

        if (more) {
            buf ^= 1;
            As[buf][acol + 0][arow] = a4n.x;
            As[buf][acol + 1][arow] = a4n.y;
            As[buf][acol + 2][arow] = a4n.z;
            As[buf][acol + 3][arow] = a4n.w;
            if (TRANSB) {
                Bs[buf][acol + 0][arow] = b4n.x;
                Bs[buf][acol + 1][arow] = b4n.y;
                Bs[buf][acol + 2][arow] = b4n.z;
                Bs[buf][acol + 3][arow] = b4n.w;
            } else {
                *(float4*)&Bs[buf][bk][bn] = b4n;
            }
            __syncthreads();
        }
    }

    // epilogue (float4 stores)
#pragma unroll
    for (int i = 0; i < 8; i++) {
        const long long row = (long long)(m0 + ty * 8 + i) * ldc;
#pragma unroll
        for (int jg = 0; jg < 2; jg++) {
            const int col = n0 + tx * 8 + jg * 4;
            float4 o;
            o.x = acc[i][jg * 4 + 0];
            o.y = acc[i][jg * 4 + 1];
            o.z = acc[i][jg * 4 + 2];
            o.w = acc[i][jg * 4 + 3];
            if (bias) {
                o.x += bias[col + 0];
                o.y += bias[col + 1];
                o.z += bias[col + 2];
                o.w += bias[col + 3];
            }
            *(float4*)(C + row + col) = o;
        }
    }
}

// ---------------- split + normalize + fold column scales into K ----------------
// grid (N, H), block 128
__global__ void split_normalize(const float* __restrict__ cls_score,
                                const float* __restrict__ fg_score)
{
    const int n = blockIdx.x, h = blockIdx.y, j = threadIdx.x;
    const float* bc = g_qkv_cls + (size_t)n * 3 * Cc + h * Dd;
    const float* br = g_qkv_reg + (size_t)n * 3 * Cc + h * Dd;

    float qc = bc[0 * Cc + j], kc = bc[1 * Cc + j], vv = bc[2 * Cc + j];
    float qr = br[0 * Cc + j], kr = br[1 * Cc + j];

    float s[5] = {qc * qc, kc * kc, vv * vv, qr * qr, kr * kr};
    __shared__ float red[5][4];
    const int lane = j & 31, warp = j >> 5;
#pragma unroll
    for (int i = 0; i < 5; i++) {
        float v = warpSum(s[i]);
        if (lane == 0) red[i][warp] = v;
    }
    __syncthreads();
    float inv[5];
#pragma unroll
    for (int i = 0; i < 5; i++)
        inv[i] = 1.0f / sqrtf(red[i][0] + red[i][1] + red[i][2] + red[i][3]);

    const float sc_c = SCALE_F * cls_score[n];
    const float sc_f = SCALE_F * fg_score[n];
    const size_t off = ((size_t)h * Nn + n) * Dd + j;
    const size_t set1 = (size_t)Hh * Nn * Dd;

    g_qn[off]        = qc * inv[0];
    g_kn[off]        = kc * inv[1] * sc_c;
    g_qn[set1 + off] = qr * inv[3];
    g_kn[set1 + off] = kr * inv[4] * sc_f;
    g_v[off]         = vv;
    g_vn[(size_t)n * Cc + h * Dd + j] = vv * inv[2];
}

// ---------------- per-row dual softmax + head combine + head-sum ----------------
// grid (N), block 256
__global__ void __launch_bounds__(256) softmax_combine()
{
    const int n = blockIdx.x, t = threadIdx.x;
    __shared__ float sc[Nn];
    __shared__ float sr[Nn];
    __shared__ float acc[Nn];
    __shared__ float red[8];

    for (int m = t; m < Nn; m += 256) acc[m] = 0.0f;

    for (int h = 0; h < Hh; h++) {
        const size_t base = ((size_t)h * Nn + n) * Nn;
        float lmc = -3.0e38f, lmr = -3.0e38f;
        for (int m = t; m < Nn; m += 256) {
            float a = g_S0[base + m];
            float b = g_S1[base + m];
            sc[m] = a; sr[m] = b;
            lmc = fmaxf(lmc, a);
            lmr = fmaxf(lmr, b);
        }
        const float mc = blockMax(lmc, red);
        const float mr = blockMax(lmr, red);
        float lsc = 0.0f, lsr = 0.0f;
        for (int m = t; m < Nn; m += 256) {
            float ec = expf(sc[m] - mc);
            float er = expf(sr[m] - mr);
            sc[m] = ec; sr[m] = er;
            lsc += ec; lsr += er;
        }
        const float ic = 0.5f / blockSum(lsc, red);
        const float ir = 0.5f / blockSum(lsr, red);
        for (int m = t; m < Nn; m += 256) {
            float p = sc[m] * ic + sr[m] * ir;
            g_S0[base + m] = p;   // combined attn prob for this head
            acc[m] += p;
        }
        __syncthreads();
    }
    for (int m = t; m < Nn; m += 256) g_attnsum[(size_t)n * Nn + m] = acc[m];
}

// ---------------- mask + softmax round 2 + renormalize ----------------
// grid (N), block 256
__global__ void __launch_bounds__(256) mask_softmax2()
{
    const int n = blockIdx.x, t = threadIdx.x;
    __shared__ float buf[Nn];
    __shared__ float red[8];

    float lm = -3.0e38f;
    for (int m = t; m < Nn; m += 256) {
        float v = g_attnsum[(size_t)n * Nn + m] * 0.125f;   // /H (exact)
        buf[m] = v;
        lm = fmaxf(lm, v);
    }
    const float mx = blockMax(lm, red);
    float ls = 0.0f;
    for (int m = t; m < Nn; m += 256) {
        float e = expf(buf[m] - mx);
        buf[m] = e;
        ls += e;
    }
    const float inv = 1.0f / blockSum(ls, red);
    float lms = 0.0f;
    for (int m = t; m < Nn; m += 256) {
        float p = buf[m] * inv;
        // sim_raw = simraw/8 > 0.75  <=>  simraw > 6 (exact: /8 is a pow2 scale)
        float keep = (g_simraw[(size_t)n * Nn + m] > 6.0f) ? p : 0.0f;
        buf[m] = keep;
        lms += keep;
    }
    const float invm = 1.0f / blockSum(lms, red);
    for (int m = t; m < Nn; m += 256) g_sim2[(size_t)n * Nn + m] = buf[m] * invm;
}

// ---------------- x_ori copy: trans_cls[:,C:2C] = v slice of qkv_cls ----------------
__global__ void copy_xori()
{
    const int idx = blockIdx.x * 256 + threadIdx.x;  // 0 .. N*C-1
    const int n = idx >> 10;
    const int c = idx & 1023;
    g_x[(size_t)n * 2 * Cc + Cc + c] = g_qkv_cls[(size_t)n * 3 * Cc + 2 * Cc + c];
}

// ---------------- launch ----------------
extern "C" void kernel_launch(void* const* d_in, const int* in_sizes, int n_in,
                              void* d_out, int out_size)
{
    const float* x_cls     = (const float*)d_in[0];
    const float* x_reg     = (const float*)d_in[1];
    const float* cls_score = (const float*)d_in[2];
    const float* fg_score  = (const float*)d_in[3];
    const float* W_qkv_cls = (const float*)d_in[4];
    const float* W_qkv_reg = (const float*)d_in[5];
    const float* W1        = (const float*)d_in[6];
    const float* b1        = (const float*)d_in[7];
    const float* W2        = (const float*)d_in[8];
    const float* b2        = (const float*)d_in[9];
    float* out = (float*)d_out;

    float *qkvc, *qkvr, *qn, *kn, *vv, *vn, *S0, *S1, *simraw, *xbuf, *sim2, *ave;
    cudaGetSymbolAddress((void**)&qkvc, g_qkv_cls);
    cudaGetSymbolAddress((void**)&qkvr, g_qkv_reg);
    cudaGetSymbolAddress((void**)&qn, g_qn);
    cudaGetSymbolAddress((void**)&kn, g_kn);
    cudaGetSymbolAddress((void**)&vv, g_v);
    cudaGetSymbolAddress((void**)&vn, g_vn);
    cudaGetSymbolAddress((void**)&S0, g_S0);
    cudaGetSymbolAddress((void**)&S1, g_S1);
    cudaGetSymbolAddress((void**)&simraw, g_simraw);
    cudaGetSymbolAddress((void**)&xbuf, g_x);
    cudaGetSymbolAddress((void**)&sim2, g_sim2);
    cudaGetSymbolAddress((void**)&ave, g_ave);

    const long long HND = (long long)Hh * Nn * Dd;
    const long long NN  = (long long)Nn * Nn;

    // 1,2: qkv projections
    gemm_f32<true><<<dim3(3 * Cc / 128, Nn / 128, 1), 256>>>(
        x_cls, W_qkv_cls, qkvc, nullptr, Nn, 3 * Cc, Cc, Cc, Cc, 3 * Cc, 0, 0, 0);
    gemm_f32<true><<<dim3(3 * Cc / 128, Nn / 128, 1), 256>>>(
        x_reg, W_qkv_reg, qkvr, nullptr, Nn, 3 * Cc, Cc, Cc, Cc, 3 * Cc, 0, 0, 0);

    // 3: split heads, normalize, fold SCALE*score into k
    split_normalize<<<dim3(Nn, Hh), 128>>>(cls_score, fg_score);

    // 4: batched score GEMMs (per head) + simraw GEMM
    gemm_f32<true><<<dim3(Nn / 128, Nn / 128, Hh), 256>>>(
        qn, kn, S0, nullptr, Nn, Nn, Dd, Dd, Dd, Nn,
        (long long)Nn * Dd, (long long)Nn * Dd, NN);
    gemm_f32<true><<<dim3(Nn / 128, Nn / 128, Hh), 256>>>(
        qn + HND, kn + HND, S1, nullptr, Nn, Nn, Dd, Dd, Dd, Nn,
        (long long)Nn * Dd, (long long)Nn * Dd, NN);
    gemm_f32<true><<<dim3(Nn / 128, Nn / 128, 1), 256>>>(
        vn, vn, simraw, nullptr, Nn, Nn, Cc, Cc, Cc, Nn, 0, 0, 0);

    // 5: dual softmax + combine heads (writes probs back into S0, head-sums to attnsum)
    softmax_combine<<<Nn, 256>>>();

    // 6: x = attn @ v (per head), columns h*d of trans_cls
    gemm_f32<false><<<dim3(1, Nn / 128, Hh), 256>>>(
        S0, vv, xbuf, nullptr, Nn, Dd, Nn, Nn, Dd, 2 * Cc,
        NN, (long long)Nn * Dd, (long long)Dd);

    // x_ori copy into trans_cls[:, C:2C]
    copy_xori<<<(Nn * Cc) / 256, 256>>>();

    // 7: feat = trans_cls @ W1^T + b1  -> ave[:, 2C:4C]
    gemm_f32<true><<<dim3(2 * Cc / 128, Nn / 128, 1), 256>>>(
        xbuf, W1, ave + 2 * Cc, b1, Nn, 2 * Cc, 2 * Cc, 2 * Cc, 2 * Cc, 4 * Cc, 0, 0, 0);

    // 8: sim_round2 (softmax + mask + renorm)
    mask_softmax2<<<Nn, 256>>>();

    // 9: soft_sim = sim_round2 @ feat -> ave[:, 0:2C]
    gemm_f32<false><<<dim3(2 * Cc / 128, Nn / 128, 1), 256>>>(
        sim2, ave + 2 * Cc, ave, nullptr, Nn, 2 * Cc, Nn, Nn, 4 * Cc, 4 * Cc, 0, 0, 0);

    // 10: out = ave @ W2^T + b2
    gemm_f32<true><<<dim3(Cc / 128, Nn / 128, 1), 256>>>(
        ave, W2, out, b2, Nn, Cc, 4 * Cc, 4 * Cc, 4 * Cc, Cc, 0, 0, 0);
}

// round 3
// speedup vs baseline: 1.0001x; 1.0001x over previous
#include <cuda_runtime.h>
#include <math.h>

#define Nn 2048
#define Cc 1024
#define Hh 8
#define Dd 128
#define SCALE_F 25.0f

// ---------------- scratch (static device globals; no allocs) ----------------
__device__ __align__(128) float g_qkv_cls[Nn * 3 * Cc];     // [N,3,H,d]
__device__ __align__(128) float g_qkv_reg[Nn * 3 * Cc];
__device__ __align__(128) float g_qn[2 * Hh * Nn * Dd];     // normalized q, [set][H][N][d]
__device__ __align__(128) float g_kn[2 * Hh * Nn * Dd];     // normalized*SCALE*score k
__device__ __align__(128) float g_v[Hh * Nn * Dd];          // raw v_cls, [H][N][d]
__device__ __align__(128) float g_vn[Nn * Cc];              // per-head-normalized v, [N, H*d]
__device__ __align__(128) float g_S0[Hh * Nn * Nn];         // cls scores -> attn probs
__device__ __align__(128) float g_S1[Hh * Nn * Nn];         // reg scores
__device__ __align__(128) float g_simraw[Nn * Nn];          // sum_h vn.vn
__device__ __align__(128) float g_attnsum[Nn * Nn];         // sum_h attn
__device__ __align__(128) float g_x[Nn * 2 * Cc];           // trans_cls = [x | x_ori]
__device__ __align__(128) float g_sim2[Nn * Nn];            // sim_round2
__device__ __align__(128) float g_ave[Nn * 4 * Cc];         // [soft_sim | feat]

// ---------------- reductions ----------------
__device__ __forceinline__ float warpMax(float v) {
#pragma unroll
    for (int o = 16; o; o >>= 1) v = fmaxf(v, __shfl_xor_sync(0xffffffffu, v, o));
    return v;
}
__device__ __forceinline__ float warpSum(float v) {
#pragma unroll
    for (int o = 16; o; o >>= 1) v += __shfl_xor_sync(0xffffffffu, v, o);
    return v;
}
// blockDim.x == 256 (8 warps)
__device__ float blockMax(float v, float* s) {
    int w = threadIdx.x >> 5, l = threadIdx.x & 31;
    v = warpMax(v);
    if (l == 0) s[w] = v;
    __syncthreads();
    float r = (l < 8) ? s[l] : -3.0e38f;
    r = warpMax(r);
    r = __shfl_sync(0xffffffffu, r, 0);
    __syncthreads();
    return r;
}
__device__ float blockSum(float v, float* s) {
    int w = threadIdx.x >> 5, l = threadIdx.x & 31;
    v = warpSum(v);
    if (l == 0) s[w] = v;
    __syncthreads();
    float r = (l < 8) ? s[l] : 0.0f;
    r = warpSum(r);
    r = __shfl_sync(0xffffffffu, r, 0);
    __syncthreads();
    return r;
}

// ---------------- SGEMM: C = A @ op(B) (+bias) ----------------
// TRANSB=true : B is [N,K] row-major (ldb)  -> C = A*B^T
// TRANSB=false: B is [K,N] row-major (ldb)  -> C = A*B
// Requires M%128==0, N%128==0, K%8==0, lda/ldb%4==0, 16B-aligned bases.
template <bool TRANSB>
__global__ void __launch_bounds__(256) gemm_f32(
    const float* __restrict__ A, const float* __restrict__ B, float* __restrict__ C,
    const float* __restrict__ bias,
    int M, int N, int K, int lda, int ldb, int ldc,
    long long sA, long long sB, long long sC)
{
    __shared__ __align__(16) float As[2][8][128];
    __shared__ __align__(16) float Bs[2][8][128];

    A += (long long)blockIdx.z * sA;
    B += (long long)blockIdx.z * sB;
    C += (long long)blockIdx.z * sC;

    const int m0 = blockIdx.y * 128;
    const int n0 = blockIdx.x * 128;
    const int t  = threadIdx.x;
    const int tx = t & 15, ty = t >> 4;

    // A-tile loader (also B when TRANSB): 128 rows x 8 k, float4 along k
    const int arow = t >> 1;
    const int acol = (t & 1) * 4;
    // B-tile loader for NN: 8 k-rows x 128 cols, float4 along n
    const int bk = t >> 5;
    const int bn = (t & 31) * 4;

    float acc[8][8];
#pragma unroll
    for (int i = 0; i < 8; i++)
#pragma unroll
        for (int j = 0; j < 8; j++) acc[i][j] = 0.0f;

    const int ntiles = K >> 3;

    // prologue: tile 0
    float4 a4 = *(const float4*)(A + (long long)(m0 + arow) * lda + acol);
    float4 b4;
    if (TRANSB) b4 = *(const float4*)(B + (long long)(n0 + arow) * ldb + acol);
    else        b4 = *(const float4*)(B + (long long)bk * ldb + n0 + bn);

    As[0][acol + 0][arow] = a4.x;
    As[0][acol + 1][arow] = a4.y;
    As[0][acol + 2][arow] = a4.z;
    As[0][acol + 3][arow] = a4.w;
    if (TRANSB) {
        Bs[0][acol + 0][arow] = b4.x;
        Bs[0][acol + 1][arow] = b4.y;
        Bs[0][acol + 2][arow] = b4.z;
        Bs[0][acol + 3][arow] = b4.w;
    } else {
        *(float4*)&Bs[0][bk][bn] = b4;
    }
    __syncthreads();

    int buf = 0;
    for (int tile = 0; tile < ntiles; ++tile) {
        float4 a4n, b4n;
        const bool more = (tile + 1 < ntiles);
        if (more) {
            const int k0 = (tile + 1) << 3;
            a4n = *(const float4*)(A + (long long)(m0 + arow) * lda + k0 + acol);
            if (TRANSB) b4n = *(const float4*)(B + (long long)(n0 + arow) * ldb + k0 + acol);
            else        b4n = *(const float4*)(B + (long long)(k0 + bk) * ldb + n0 + bn);
        }

#pragma unroll
        for (int kk = 0; kk < 8; kk++) {
            float ar[8], br[8];
            *(float4*)&ar[0] = *(const float4*)&As[buf][kk][ty * 8];
            *(float4*)&ar[4] = *(const float4*)&As[buf][kk][ty * 8 + 4];
            *(float4*)&br[0] = *(const float4*)&Bs[buf][kk][tx * 8];
            *(float4*)&br[4] = *(const float4*)&Bs[buf][kk][tx * 8 + 4];
#pragma unroll
            for (int i = 0; i < 8; i++)
#pragma unroll
                for (int j = 0; j < 8; j++) acc[i][j] = fmaf(ar[i], br[j], acc[i][j]);
        }

        if (more) {
            buf ^= 1;
            As[buf][acol + 0][arow] = a4n.x;
            As[buf][acol + 1][arow] = a4n.y;
            As[buf][acol + 2][arow] = a4n.z;
            As[buf][acol + 3][arow] = a4n.w;
            if (TRANSB) {
                Bs[buf][acol + 0][arow] = b4n.x;
                Bs[buf][acol + 1][arow] = b4n.y;
                Bs[buf][acol + 2][arow] = b4n.z;
                Bs[buf][acol + 3][arow] = b4n.w;
            } else {
                *(float4*)&Bs[buf][bk][bn] = b4n;
            }
            __syncthreads();
        }
    }

    // epilogue (float4 stores)
#pragma unroll
    for (int i = 0; i < 8; i++) {
        const long long row = (long long)(m0 + ty * 8 + i) * ldc;
#pragma unroll
        for (int jg = 0; jg < 2; jg++) {
            const int col = n0 + tx * 8 + jg * 4;
            float4 o;
            o.x = acc[i][jg * 4 + 0];
            o.y = acc[i][jg * 4 + 1];
            o.z = acc[i][jg * 4 + 2];
            o.w = acc[i][jg * 4 + 3];
            if (bias) {
                o.x += bias[col + 0];
                o.y += bias[col + 1];
                o.z += bias[col + 2];
                o.w += bias[col + 3];
            }
            *(float4*)(C + row + col) = o;
        }
    }
}

// ---------------- split + normalize + fold column scales into K ----------------
// grid (N, H), block 128
__global__ void split_normalize(const float* __restrict__ cls_score,
                                const float* __restrict__ fg_score)
{
    const int n = blockIdx.x, h = blockIdx.y, j = threadIdx.x;
    const float* bc = g_qkv_cls + (size_t)n * 3 * Cc + h * Dd;
    const float* br = g_qkv_reg + (size_t)n * 3 * Cc + h * Dd;

    float qc = bc[0 * Cc + j], kc = bc[1 * Cc + j], vv = bc[2 * Cc + j];
    float qr = br[0 * Cc + j], kr = br[1 * Cc + j];

    float s[5] = {qc * qc, kc * kc, vv * vv, qr * qr, kr * kr};
    __shared__ float red[5][4];
    const int lane = j & 31, warp = j >> 5;
#pragma unroll
    for (int i = 0; i < 5; i++) {
        float v = warpSum(s[i]);
        if (lane == 0) red[i][warp] = v;
    }
    __syncthreads();
    float inv[5];
#pragma unroll
    for (int i = 0; i < 5; i++)
        inv[i] = 1.0f / sqrtf(red[i][0] + red[i][1] + red[i][2] + red[i][3]);

    const float sc_c = SCALE_F * cls_score[n];
    const float sc_f = SCALE_F * fg_score[n];
    const size_t off = ((size_t)h * Nn + n) * Dd + j;
    const size_t set1 = (size_t)Hh * Nn * Dd;

    g_qn[off]        = qc * inv[0];
    g_kn[off]        = kc * inv[1] * sc_c;
    g_qn[set1 + off] = qr * inv[3];
    g_kn[set1 + off] = kr * inv[4] * sc_f;
    g_v[off]         = vv;
    g_vn[(size_t)n * Cc + h * Dd + j] = vv * inv[2];
}

// ---------------- per-row dual softmax + head combine + head-sum ----------------
// grid (N), block 256
__global__ void __launch_bounds__(256) softmax_combine()
{
    const int n = blockIdx.x, t = threadIdx.x;
    __shared__ float sc[Nn];
    __shared__ float sr[Nn];
    __shared__ float acc[Nn];
    __shared__ float red[8];

    for (int m = t; m < Nn; m += 256) acc[m] = 0.0f;

    for (int h = 0; h < Hh; h++) {
        const size_t base = ((size_t)h * Nn + n) * Nn;
        float lmc = -3.0e38f, lmr = -3.0e38f;
        for (int m = t; m < Nn; m += 256) {
            float a = g_S0[base + m];
            float b = g_S1[base + m];
            sc[m] = a; sr[m] = b;
            lmc = fmaxf(lmc, a);
            lmr = fmaxf(lmr, b);
        }
        const float mc = blockMax(lmc, red);
        const float mr = blockMax(lmr, red);
        float lsc = 0.0f, lsr = 0.0f;
        for (int m = t; m < Nn; m += 256) {
            float ec = expf(sc[m] - mc);
            float er = expf(sr[m] - mr);
            sc[m] = ec; sr[m] = er;
            lsc += ec; lsr += er;
        }
        const float ic = 0.5f / blockSum(lsc, red);
        const float ir = 0.5f / blockSum(lsr, red);
        for (int m = t; m < Nn; m += 256) {
            float p = sc[m] * ic + sr[m] * ir;
            g_S0[base + m] = p;   // combined attn prob for this head
            acc[m] += p;
        }
        __syncthreads();
    }
    for (int m = t; m < Nn; m += 256) g_attnsum[(size_t)n * Nn + m] = acc[m];
}

// ---------------- mask + softmax round 2 + renormalize ----------------
// grid (N), block 256
__global__ void __launch_bounds__(256) mask_softmax2()
{
    const int n = blockIdx.x, t = threadIdx.x;
    __shared__ float buf[Nn];
    __shared__ float red[8];

    float lm = -3.0e38f;
    for (int m = t; m < Nn; m += 256) {
        float v = g_attnsum[(size_t)n * Nn + m] * 0.125f;   // /H (exact)
        buf[m] = v;
        lm = fmaxf(lm, v);
    }
    const float mx = blockMax(lm, red);
    float ls = 0.0f;
    for (int m = t; m < Nn; m += 256) {
        float e = expf(buf[m] - mx);
        buf[m] = e;
        ls += e;
    }
    const float inv = 1.0f / blockSum(ls, red);
    float lms = 0.0f;
    for (int m = t; m < Nn; m += 256) {
        float p = buf[m] * inv;
        // sim_raw = simraw/8 > 0.75  <=>  simraw > 6 (exact: /8 is a pow2 scale)
        float keep = (g_simraw[(size_t)n * Nn + m] > 6.0f) ? p : 0.0f;
        buf[m] = keep;
        lms += keep;
    }
    const float invm = 1.0f / blockSum(lms, red);
    for (int m = t; m < Nn; m += 256) g_sim2[(size_t)n * Nn + m] = buf[m] * invm;
}

// ---------------- x_ori copy: trans_cls[:,C:2C] = v slice of qkv_cls ----------------
__global__ void copy_xori()
{
    const int idx = blockIdx.x * 256 + threadIdx.x;  // 0 .. N*C-1
    const int n = idx >> 10;
    const int c = idx & 1023;
    g_x[(size_t)n * 2 * Cc + Cc + c] = g_qkv_cls[(size_t)n * 3 * Cc + 2 * Cc + c];
}

// ---------------- launch ----------------
extern "C" void kernel_launch(void* const* d_in, const int* in_sizes, int n_in,
                              void* d_out, int out_size)
{
    const float* x_cls     = (const float*)d_in[0];
    const float* x_reg     = (const float*)d_in[1];
    const float* cls_score = (const float*)d_in[2];
    const float* fg_score  = (const float*)d_in[3];
    const float* W_qkv_cls = (const float*)d_in[4];
    const float* W_qkv_reg = (const float*)d_in[5];
    const float* W1        = (const float*)d_in[6];
    const float* b1        = (const float*)d_in[7];
    const float* W2        = (const float*)d_in[8];
    const float* b2        = (const float*)d_in[9];
    float* out = (float*)d_out;

    float *qkvc, *qkvr, *qn, *kn, *vv, *vn, *S0, *S1, *simraw, *xbuf, *sim2, *ave;
    cudaGetSymbolAddress((void**)&qkvc, g_qkv_cls);
    cudaGetSymbolAddress((void**)&qkvr, g_qkv_reg);
    cudaGetSymbolAddress((void**)&qn, g_qn);
    cudaGetSymbolAddress((void**)&kn, g_kn);
    cudaGetSymbolAddress((void**)&vv, g_v);
    cudaGetSymbolAddress((void**)&vn, g_vn);
    cudaGetSymbolAddress((void**)&S0, g_S0);
    cudaGetSymbolAddress((void**)&S1, g_S1);
    cudaGetSymbolAddress((void**)&simraw, g_simraw);
    cudaGetSymbolAddress((void**)&xbuf, g_x);
    cudaGetSymbolAddress((void**)&sim2, g_sim2);
    cudaGetSymbolAddress((void**)&ave, g_ave);

    const long long HND = (long long)Hh * Nn * Dd;
    const long long NN  = (long long)Nn * Nn;

    // 1,2: qkv projections
    gemm_f32<true><<<dim3(3 * Cc / 128, Nn / 128, 1), 256>>>(
        x_cls, W_qkv_cls, qkvc, nullptr, Nn, 3 * Cc, Cc, Cc, Cc, 3 * Cc, 0, 0, 0);
    gemm_f32<true><<<dim3(3 * Cc / 128, Nn / 128, 1), 256>>>(
        x_reg, W_qkv_reg, qkvr, nullptr, Nn, 3 * Cc, Cc, Cc, Cc, 3 * Cc, 0, 0, 0);

    // 3: split heads, normalize, fold SCALE*score into k
    split_normalize<<<dim3(Nn, Hh), 128>>>(cls_score, fg_score);

    // 4: batched score GEMMs (per head) + simraw GEMM
    gemm_f32<true><<<dim3(Nn / 128, Nn / 128, Hh), 256>>>(
        qn, kn, S0, nullptr, Nn, Nn, Dd, Dd, Dd, Nn,
        (long long)Nn * Dd, (long long)Nn * Dd, NN);
    gemm_f32<true><<<dim3(Nn / 128, Nn / 128, Hh), 256>>>(
        qn + HND, kn + HND, S1, nullptr, Nn, Nn, Dd, Dd, Dd, Nn,
        (long long)Nn * Dd, (long long)Nn * Dd, NN);
    gemm_f32<true><<<dim3(Nn / 128, Nn / 128, 1), 256>>>(
        vn, vn, simraw, nullptr, Nn, Nn, Cc, Cc, Cc, Nn, 0, 0, 0);

    // 5: dual softmax + combine heads (writes probs back into S0, head-sums to attnsum)
    softmax_combine<<<Nn, 256>>>();

    // 6: x = attn @ v (per head), columns h*d of trans_cls
    gemm_f32<false><<<dim3(1, Nn / 128, Hh), 256>>>(
        S0, vv, xbuf, nullptr, Nn, Dd, Nn, Nn, Dd, 2 * Cc,
        NN, (long long)Nn * Dd, (long long)Dd);

    // x_ori copy into trans_cls[:, C:2C]
    copy_xori<<<(Nn * Cc) / 256, 256>>>();

    // 7: feat = trans_cls @ W1^T + b1  -> ave[:, 2C:4C]
    gemm_f32<true><<<dim3(2 * Cc / 128, Nn / 128, 1), 256>>>(
        xbuf, W1, ave + 2 * Cc, b1, Nn, 2 * Cc, 2 * Cc, 2 * Cc, 2 * Cc, 4 * Cc, 0, 0, 0);

    // 8: sim_round2 (softmax + mask + renorm)
    mask_softmax2<<<Nn, 256>>>();

    // 9: soft_sim = sim_round2 @ feat -> ave[:, 0:2C]
    gemm_f32<false><<<dim3(2 * Cc / 128, Nn / 128, 1), 256>>>(
        sim2, ave + 2 * Cc, ave, nullptr, Nn, 2 * Cc, Nn, Nn, 4 * Cc, 4 * Cc, 0, 0, 0);

    // 10: out = ave @ W2^T + b2
    gemm_f32<true><<<dim3(Cc / 128, Nn / 128, 1), 256>>>(
        ave, W2, out, b2, Nn, Cc, 4 * Cc, 4 * Cc, 4 * Cc, Cc, 0, 0, 0);
}

// round 5
// speedup vs baseline: 2.4956x; 2.4953x over previous
#include <cuda_runtime.h>
#include <cuda_fp16.h>
#include <math.h>
#include <stdint.h>

#define Nn 2048
#define Cc 1024
#define Hh 8
#define Dd 128
#define SCALE_F 25.0f

typedef __half h16;

// ---------------- fp32 scratch ----------------
__device__ __align__(128) float g_qkv_cls[Nn * 3 * Cc];
__device__ __align__(128) float g_qkv_reg[Nn * 3 * Cc];
__device__ __align__(128) float g_v[Hh * Nn * Dd];
__device__ __align__(128) float g_S0[(size_t)Hh * Nn * Nn];
__device__ __align__(128) float g_S1[(size_t)Hh * Nn * Nn];
__device__ __align__(128) float g_simraw[Nn * Nn];
__device__ __align__(128) float g_attnsum[Nn * Nn];
__device__ __align__(128) float g_x[Nn * 2 * Cc];
__device__ __align__(128) float g_ave[Nn * 4 * Cc];

// ---------------- split-fp16 operands (A=[hi|lo], B=[hi|hi] along K) ----------------
__device__ __align__(128) h16 g_xclsA2[Nn * 2 * Cc];
__device__ __align__(128) h16 g_xregA2[Nn * 2 * Cc];
__device__ __align__(128) h16 g_WqcB2[3 * Cc * 2 * Cc];
__device__ __align__(128) h16 g_WqrB2[3 * Cc * 2 * Cc];
__device__ __align__(128) h16 g_qnA2[2 * Hh * Nn * 2 * Dd];
__device__ __align__(128) h16 g_knB2[2 * Hh * Nn * 2 * Dd];
__device__ __align__(128) h16 g_vT2[Hh * Dd * 2 * Nn];
__device__ __align__(128) h16 g_vnA2[Nn * 2 * Cc];
__device__ __align__(128) h16 g_vnB2[Nn * 2 * Cc];
__device__ __align__(128) h16 g_attnA2[(size_t)Hh * Nn * 2 * Nn];
__device__ __align__(128) h16 g_xA2[Nn * 4 * Cc];
__device__ __align__(128) h16 g_sim2A2[Nn * 2 * Nn];
__device__ __align__(128) h16 g_featB2[2 * Cc * 2 * Nn];
__device__ __align__(128) h16 g_aveA2[Nn * 8 * Cc];
__device__ __align__(128) h16 g_W1B2[2 * Cc * 4 * Cc];
__device__ __align__(128) h16 g_W2B2[Cc * 8 * Cc];

// ---------------- helpers ----------------
__device__ __forceinline__ float warpMax(float v) {
#pragma unroll
    for (int o = 16; o; o >>= 1) v = fmaxf(v, __shfl_xor_sync(0xffffffffu, v, o));
    return v;
}
__device__ __forceinline__ float warpSum(float v) {
#pragma unroll
    for (int o = 16; o; o >>= 1) v += __shfl_xor_sync(0xffffffffu, v, o);
    return v;
}
__device__ float blockMax(float v, float* s) {
    int w = threadIdx.x >> 5, l = threadIdx.x & 31;
    v = warpMax(v);
    if (l == 0) s[w] = v;
    __syncthreads();
    float r = (l < 8) ? s[l] : -3.0e38f;
    r = warpMax(r);
    r = __shfl_sync(0xffffffffu, r, 0);
    __syncthreads();
    return r;
}
__device__ float blockSum(float v, float* s) {
    int w = threadIdx.x >> 5, l = threadIdx.x & 31;
    v = warpSum(v);
    if (l == 0) s[w] = v;
    __syncthreads();
    float r = (l < 8) ? s[l] : 0.0f;
    r = warpSum(r);
    r = __shfl_sync(0xffffffffu, r, 0);
    __syncthreads();
    return r;
}
__device__ __forceinline__ void splith(float x, h16& h, h16& l) {
    h = __float2half_rn(x);
    l = __float2half_rn(x - __half2float(h));
}
__device__ __forceinline__ uint32_t smem_u32(const void* p) {
    uint32_t a;
    asm("{ .reg .u64 t; cvta.to.shared.u64 t, %1; cvt.u32.u64 %0, t; }" : "=r"(a) : "l"(p));
    return a;
}
__device__ __forceinline__ void cp16(uint32_t s, const void* g) {
    asm volatile("cp.async.cg.shared.global [%0], [%1], 16;" :: "r"(s), "l"(g) : "memory");
}
__device__ __forceinline__ uint32_t swz(uint32_t off) {
    return off ^ ((off >> 3) & 0x70);
}
__device__ __forceinline__ void ldsm4(uint32_t* r, uint32_t a) {
    asm volatile("ldmatrix.sync.aligned.m8n8.x4.shared.b16 {%0,%1,%2,%3}, [%4];"
                 : "=r"(r[0]), "=r"(r[1]), "=r"(r[2]), "=r"(r[3]) : "r"(a));
}
__device__ __forceinline__ void mma16816(float* c, const uint32_t* a, uint32_t b0, uint32_t b1) {
    asm volatile(
        "mma.sync.aligned.m16n8k16.row.col.f32.f16.f16.f32 "
        "{%0,%1,%2,%3},{%4,%5,%6,%7},{%8,%9},{%0,%1,%2,%3};"
        : "+f"(c[0]), "+f"(c[1]), "+f"(c[2]), "+f"(c[3])
        : "r"(a[0]), "r"(a[1]), "r"(a[2]), "r"(a[3]), "r"(b0), "r"(b1));
}

// ---------------- HMMA GEMM: C[128x128](f32) = A[M,K2] * B[N,K2]^T (fp16) ----------------
#define TILE_BYTES 16384
#define GSMEM (4 * TILE_BYTES)

__global__ void __launch_bounds__(256, 2) gemm_mma(
    const h16* __restrict__ A, const h16* __restrict__ B, float* __restrict__ C,
    const float* __restrict__ bias, int K2, int ldc,
    long long sA, long long sB, long long sC)
{
    extern __shared__ char smem[];
    const uint32_t sbase = smem_u32(smem);
    const int t = threadIdx.x, lane = t & 31, wid = t >> 5;
    const int wm = (wid & 3) * 32, wn = (wid >> 2) * 64;

    A += (long long)blockIdx.z * sA;
    B += (long long)blockIdx.z * sB;
    C += (long long)blockIdx.z * sC;
    const int m0 = blockIdx.y * 128, n0 = blockIdx.x * 128;

    const uint32_t aB[2] = {sbase, sbase + 2 * TILE_BYTES};
    const uint32_t bB[2] = {sbase + TILE_BYTES, sbase + 3 * TILE_BYTES};

    // loader: thread t covers row t>>1, 64-byte half (t&1), 4x 16B
    uint32_t ld_sw[4];
#pragma unroll
    for (int s = 0; s < 4; s++) {
        uint32_t off = (uint32_t)(t >> 1) * 128 + (uint32_t)(t & 1) * 64 + s * 16;
        ld_sw[s] = swz(off);
    }
    const h16* Ag = A + (long long)(m0 + (t >> 1)) * K2 + (t & 1) * 32;
    const h16* Bg = B + (long long)(n0 + (t >> 1)) * K2 + (t & 1) * 32;

    auto LOAD = [&](int st, int ch) {
#pragma unroll
        for (int s = 0; s < 4; s++) {
            cp16(aB[st] + ld_sw[s], Ag + ch * 64 + s * 8);
            cp16(bB[st] + ld_sw[s], Bg + ch * 64 + s * 8);
        }
        asm volatile("cp.async.commit_group;" ::: "memory");
    };

    // ldmatrix per-lane row/byte pattern
    const uint32_t frow = (lane & 7) + ((lane >> 3) & 1) * 8;
    const uint32_t fbyte = (lane >> 4) * 16;

    float acc[2][8][4];
#pragma unroll
    for (int i = 0; i < 2; i++)
#pragma unroll
        for (int j = 0; j < 8; j++)
#pragma unroll
            for (int q = 0; q < 4; q++) acc[i][j][q] = 0.0f;

    const int nch = K2 >> 6;
    LOAD(0, 0);
    LOAD(1, 1);

    for (int c = 0; c < nch; ++c) {
        const int st = c & 1;
        asm volatile("cp.async.wait_group 1;" ::: "memory");
        __syncthreads();
#pragma unroll
        for (int ks = 0; ks < 4; ks++) {
            uint32_t af[2][4], bf[4][4];
#pragma unroll
            for (int i = 0; i < 2; i++)
                ldsm4(af[i], aB[st] + swz((wm + i * 16 + frow) * 128 + ks * 32 + fbyte));
#pragma unroll
            for (int jn = 0; jn < 4; jn++)
                ldsm4(bf[jn], bB[st] + swz((wn + jn * 16 + frow) * 128 + ks * 32 + fbyte));
#pragma unroll
            for (int i = 0; i < 2; i++)
#pragma unroll
                for (int j = 0; j < 8; j++) {
                    const int jn = j >> 1, sel = j & 1;
                    mma16816(acc[i][j], af[i], bf[jn][sel], bf[jn][sel + 2]);
                }
        }
        __syncthreads();
        if (c + 2 < nch) LOAD(st, c + 2);
    }

    // epilogue
    const int g = lane >> 2, tc = (lane & 3) * 2;
#pragma unroll
    for (int i = 0; i < 2; i++) {
        const int r0 = m0 + wm + i * 16 + g;
#pragma unroll
        for (int j = 0; j < 8; j++) {
            const int col = n0 + wn + j * 8 + tc;
            float bx = 0.0f, by = 0.0f;
            if (bias) { bx = bias[col]; by = bias[col + 1]; }
            float2 o0 = {acc[i][j][0] + bx, acc[i][j][1] + by};
            float2 o1 = {acc[i][j][2] + bx, acc[i][j][3] + by};
            *(float2*)(C + (long long)r0 * ldc + col) = o0;
            *(float2*)(C + (long long)(r0 + 8) * ldc + col) = o1;
        }
    }
}

// ---------------- converts ----------------
// A-split: [hi | lo]
__global__ void cvtA(const float* __restrict__ src, h16* __restrict__ dst, int K, int lda) {
    const size_t r = blockIdx.x;
    for (int j = threadIdx.x; j < K; j += blockDim.x) {
        h16 h, l;
        splith(src[r * lda + j], h, l);
        h16* d = dst + r * 2 * K + j;
        d[0] = h; d[K] = l;
    }
}
// B-split: [hi | hi]
__global__ void cvtB(const float* __restrict__ src, h16* __restrict__ dst, int K, int lda) {
    const size_t r = blockIdx.x;
    for (int j = threadIdx.x; j < K; j += blockDim.x) {
        h16 h = __float2half_rn(src[r * lda + j]);
        h16* d = dst + r * 2 * K + j;
        d[0] = h; d[K] = h;
    }
}
// transpose + B-split: src [R x Cl](lda) -> dst [Cl][2R] (hi|hi)
__global__ void cvtBT(const float* __restrict__ src, h16* __restrict__ dst,
                      int R, int Cl, int lda, long long sSrc, long long sDst) {
    src += (long long)blockIdx.z * sSrc;
    dst += (long long)blockIdx.z * sDst;
    __shared__ float tile[32][33];
    const int c0 = blockIdx.x * 32, r0 = blockIdx.y * 32;
    const int tx = threadIdx.x, ty = threadIdx.y;
#pragma unroll
    for (int i = 0; i < 32; i += 8)
        tile[ty + i][tx] = src[(long long)(r0 + ty + i) * lda + c0 + tx];
    __syncthreads();
#pragma unroll
    for (int i = 0; i < 32; i += 8) {
        const int c = c0 + ty + i, r = r0 + tx;
        h16 h = __float2half_rn(tile[tx][ty + i]);
        h16* d = dst + (long long)c * 2 * R + r;
        d[0] = h; d[R] = h;
    }
}

// ---------------- split + normalize + fold scales ----------------
__global__ void split_normalize(const float* __restrict__ cls_score,
                                const float* __restrict__ fg_score) {
    const int n = blockIdx.x, h = blockIdx.y, j = threadIdx.x;
    const float* bc = g_qkv_cls + (size_t)n * 3 * Cc + h * Dd + j;
    const float* br = g_qkv_reg + (size_t)n * 3 * Cc + h * Dd + j;
    float qc = bc[0], kc = bc[Cc], vv = bc[2 * Cc];
    float qr = br[0], kr = br[Cc];

    float sq[5] = {qc * qc, kc * kc, vv * vv, qr * qr, kr * kr};
    __shared__ float red[5][4];
    const int lane = j & 31, warp = j >> 5;
#pragma unroll
    for (int i = 0; i < 5; i++) {
        float v = warpSum(sq[i]);
        if (lane == 0) red[i][warp] = v;
    }
    __syncthreads();
    float inv[5];
#pragma unroll
    for (int i = 0; i < 5; i++)
        inv[i] = 1.0f / sqrtf(red[i][0] + red[i][1] + red[i][2] + red[i][3]);

    const float sc_c = SCALE_F * cls_score[n];
    const float sc_f = SCALE_F * fg_score[n];
    h16 h0, l0;

    const size_t qb0 = ((size_t)h * Nn + n) * 256;
    const size_t qb1 = ((size_t)(Hh + h) * Nn + n) * 256;
    splith(qc * inv[0], h0, l0);
    g_qnA2[qb0 + j] = h0; g_qnA2[qb0 + 128 + j] = l0;
    h0 = __float2half_rn(kc * inv[1] * sc_c);
    g_knB2[qb0 + j] = h0; g_knB2[qb0 + 128 + j] = h0;
    splith(qr * inv[3], h0, l0);
    g_qnA2[qb1 + j] = h0; g_qnA2[qb1 + 128 + j] = l0;
    h0 = __float2half_rn(kr * inv[4] * sc_f);
    g_knB2[qb1 + j] = h0; g_knB2[qb1 + 128 + j] = h0;

    g_v[((size_t)h * Nn + n) * Dd + j] = vv;
    g_x[(size_t)n * 2 * Cc + Cc + h * Dd + j] = vv;  // x_ori

    const size_t vb = (size_t)n * 2048 + h * Dd + j;
    splith(vv * inv[2], h0, l0);
    g_vnA2[vb] = h0; g_vnA2[vb + 1024] = l0;
    g_vnB2[vb] = h0; g_vnB2[vb + 1024] = h0;
}

// ---------------- dual softmax + combine + head-sum; writes attn as A-split fp16 ----------------
__global__ void __launch_bounds__(256) softmax_combine() {
    const int n = blockIdx.x, t = threadIdx.x;
    __shared__ float sc[Nn], sr[Nn], acc[Nn], red[8];
    for (int m = t; m < Nn; m += 256) acc[m] = 0.0f;
    for (int h = 0; h < Hh; h++) {
        const size_t base = ((size_t)h * Nn + n) * Nn;
        float lmc = -3.0e38f, lmr = -3.0e38f;
        for (int m = t; m < Nn; m += 256) {
            float a = g_S0[base + m], b = g_S1[base + m];
            sc[m] = a; sr[m] = b;
            lmc = fmaxf(lmc, a);
            lmr = fmaxf(lmr, b);
        }
        const float mc = blockMax(lmc, red), mr = blockMax(lmr, red);
        float lsc = 0.0f, lsr = 0.0f;
        for (int m = t; m < Nn; m += 256) {
            float ec = expf(sc[m] - mc), er = expf(sr[m] - mr);
            sc[m] = ec; sr[m] = er;
            lsc += ec; lsr += er;
        }
        const float ic = 0.5f / blockSum(lsc, red);
        const float ir = 0.5f / blockSum(lsr, red);
        h16* ab = g_attnA2 + ((size_t)h * Nn + n) * 2 * Nn;
        for (int m = t; m < Nn; m += 256) {
            float p = sc[m] * ic + sr[m] * ir;
            acc[m] += p;
            h16 hh, ll;
            splith(p, hh, ll);
            ab[m] = hh; ab[Nn + m] = ll;
        }
        __syncthreads();
    }
    for (int m = t; m < Nn; m += 256) g_attnsum[(size_t)n * Nn + m] = acc[m];
}

// ---------------- mask + softmax2 + renorm; writes sim2 as A-split fp16 ----------------
__global__ void __launch_bounds__(256) mask_softmax2() {
    const int n = blockIdx.x, t = threadIdx.x;
    __shared__ float buf[Nn], red[8];
    float lm = -3.0e38f;
    for (int m = t; m < Nn; m += 256) {
        float v = g_attnsum[(size_t)n * Nn + m] * 0.125f;
        buf[m] = v;
        lm = fmaxf(lm, v);
    }
    const float mx = blockMax(lm, red);
    float ls = 0.0f;
    for (int m = t; m < Nn; m += 256) {
        float e = expf(buf[m] - mx);
        buf[m] = e;
        ls += e;
    }
    const float inv = 1.0f / blockSum(ls, red);
    float lms = 0.0f;
    for (int m = t; m < Nn; m += 256) {
        float p = buf[m] * inv;
        float keep = (g_simraw[(size_t)n * Nn + m] > 6.0f) ? p : 0.0f;
        buf[m] = keep;
        lms += keep;
    }
    const float invm = 1.0f / blockSum(lms, red);
    h16* sb = g_sim2A2 + (size_t)n * 2 * Nn;
    for (int m = t; m < Nn; m += 256) {
        h16 hh, ll;
        splith(buf[m] * invm, hh, ll);
        sb[m] = hh; sb[Nn + m] = ll;
    }
}

// ---------------- launch ----------------
extern "C" void kernel_launch(void* const* d_in, const int* in_sizes, int n_in,
                              void* d_out, int out_size)
{
    const float* x_cls     = (const float*)d_in[0];
    const float* x_reg     = (const float*)d_in[1];
    const float* cls_score = (const float*)d_in[2];
    const float* fg_score  = (const float*)d_in[3];
    const float* W_qkv_cls = (const float*)d_in[4];
    const float* W_qkv_reg = (const float*)d_in[5];
    const float* W1        = (const float*)d_in[6];
    const float* b1        = (const float*)d_in[7];
    const float* W2        = (const float*)d_in[8];
    const float* b2        = (const float*)d_in[9];
    float* out = (float*)d_out;

    cudaFuncSetAttribute(gemm_mma, cudaFuncAttributeMaxDynamicSharedMemorySize, GSMEM);

#define ADDR(sym, var) float* var; cudaGetSymbolAddress((void**)&var, sym)
    ADDR(g_qkv_cls, qkvc); ADDR(g_qkv_reg, qkvr); ADDR(g_v, vraw);
    ADDR(g_S0, S0); ADDR(g_S1, S1); ADDR(g_simraw, simraw);
    ADDR(g_x, xbuf); ADDR(g_ave, ave);
#undef ADDR
#define HADDR(sym, var) h16* var; cudaGetSymbolAddress((void**)&var, sym)
    HADDR(g_xclsA2, xclsA2); HADDR(g_xregA2, xregA2);
    HADDR(g_WqcB2, WqcB2); HADDR(g_WqrB2, WqrB2);
    HADDR(g_qnA2, qnA2); HADDR(g_knB2, knB2); HADDR(g_vT2, vT2);
    HADDR(g_vnA2, vnA2); HADDR(g_vnB2, vnB2); HADDR(g_attnA2, attnA2);
    HADDR(g_xA2, xA2); HADDR(g_sim2A2, sim2A2); HADDR(g_featB2, featB2);
    HADDR(g_aveA2, aveA2); HADDR(g_W1B2, W1B2); HADDR(g_W2B2, W2B2);
#undef HADDR

    const long long NN = (long long)Nn * Nn;

    // converts for projections/weights
    cvtA<<<Nn, 256>>>(x_cls, xclsA2, Cc, Cc);
    cvtA<<<Nn, 256>>>(x_reg, xregA2, Cc, Cc);
    cvtB<<<3 * Cc, 256>>>(W_qkv_cls, WqcB2, Cc, Cc);
    cvtB<<<3 * Cc, 256>>>(W_qkv_reg, WqrB2, Cc, Cc);
    cvtB<<<2 * Cc, 256>>>(W1, W1B2, 2 * Cc, 2 * Cc);
    cvtB<<<Cc, 256>>>(W2, W2B2, 4 * Cc, 4 * Cc);

    // qkv projections  (K2 = 2048)
    gemm_mma<<<dim3(24, 16, 1), 256, GSMEM>>>(xclsA2, WqcB2, qkvc, nullptr, 2 * Cc, 3 * Cc, 0, 0, 0);
    gemm_mma<<<dim3(24, 16, 1), 256, GSMEM>>>(xregA2, WqrB2, qkvr, nullptr, 2 * Cc, 3 * Cc, 0, 0, 0);

    split_normalize<<<dim3(Nn, Hh), 128>>>(cls_score, fg_score);
    cvtBT<<<dim3(4, 64, 8), dim3(32, 8)>>>(vraw, vT2, Nn, Dd, Dd,
                                           (long long)Nn * Dd, (long long)Dd * 2 * Nn);

    // scores (K2 = 256 per head)
    const long long sQ = (long long)Nn * 256;
    gemm_mma<<<dim3(16, 16, 8), 256, GSMEM>>>(qnA2, knB2, S0, nullptr, 256, Nn, sQ, sQ, NN);
    gemm_mma<<<dim3(16, 16, 8), 256, GSMEM>>>(qnA2 + (size_t)Hh * Nn * 256,
                                              knB2 + (size_t)Hh * Nn * 256,
                                              S1, nullptr, 256, Nn, sQ, sQ, NN);
    // simraw (K2 = 2048)
    gemm_mma<<<dim3(16, 16, 1), 256, GSMEM>>>(vnA2, vnB2, simraw, nullptr, 2 * Cc, Nn, 0, 0, 0);

    softmax_combine<<<Nn, 256>>>();

    // x = attn @ v per head -> g_x[:, 0:C]  (K2 = 4096, N-tile 128 = Dd)
    gemm_mma<<<dim3(1, 16, 8), 256, GSMEM>>>(attnA2, vT2, xbuf, nullptr, 2 * Nn, 2 * Cc,
                                             (long long)Nn * 2 * Nn,
                                             (long long)Dd * 2 * Nn, (long long)Dd);
    cvtA<<<Nn, 256>>>(xbuf, xA2, 2 * Cc, 2 * Cc);

    // feat = trans_cls @ W1^T + b1 -> ave[:, 2C:4C]  (K2 = 4096)
    gemm_mma<<<dim3(16, 16, 1), 256, GSMEM>>>(xA2, W1B2, ave + 2 * Cc, b1, 4 * Cc, 4 * Cc, 0, 0, 0);

    mask_softmax2<<<Nn, 256>>>();
    cvtBT<<<dim3(64, 64, 1), dim3(32, 8)>>>(ave + 2 * Cc, featB2, Nn, 2 * Cc, 4 * Cc, 0, 0);

    // soft_sim = sim2 @ feat -> ave[:, 0:2C]  (K2 = 4096)
    gemm_mma<<<dim3(16, 16, 1), 256, GSMEM>>>(sim2A2, featB2, ave, nullptr, 2 * Nn, 4 * Cc, 0, 0, 0);

    cvtA<<<Nn, 256>>>(ave, aveA2, 4 * Cc, 4 * Cc);
    // out = ave @ W2^T + b2  (K2 = 8192)
    gemm_mma<<<dim3(8, 16, 1), 256, GSMEM>>>(aveA2, W2B2, out, b2, 8 * Cc, Cc, 0, 0, 0);
}

// round 6
// speedup vs baseline: 2.7947x; 1.1199x over previous
#include <cuda_runtime.h>
#include <cuda_fp16.h>
#include <math.h>
#include <stdint.h>

#define Nn 2048
#define Cc 1024
#define Hh 8
#define Dd 128
#define SCALE_F 25.0f

typedef __half h16;

// ---------------- fp32 scratch ----------------
__device__ __align__(128) float g_qkv_cls[Nn * 3 * Cc];
__device__ __align__(128) float g_qkv_reg[Nn * 3 * Cc];
__device__ __align__(128) float g_v[Hh * Nn * Dd];
__device__ __align__(128) float g_S0[(size_t)Hh * Nn * Nn];
__device__ __align__(128) float g_S1[(size_t)Hh * Nn * Nn];
__device__ __align__(128) float g_simraw[Nn * Nn];
__device__ __align__(128) float g_attnsum[Nn * Nn];
__device__ __align__(128) float g_feat[Nn * 2 * Cc];

// ---------------- fp16 operands ----------------
// A-form: per row [hi(K) | lo(K)], stride 2K.  B-form: plain [N, K].
__device__ __align__(128) h16 g_xclsA2[Nn * 2 * Cc];
__device__ __align__(128) h16 g_xregA2[Nn * 2 * Cc];
__device__ __align__(128) h16 g_WqcB[3 * Cc * Cc];
__device__ __align__(128) h16 g_WqrB[3 * Cc * Cc];
__device__ __align__(128) h16 g_qnA2[2 * Hh * Nn * 2 * Dd];
__device__ __align__(128) h16 g_knB[2 * Hh * Nn * Dd];
__device__ __align__(128) h16 g_vT[Hh * Dd * Nn];
__device__ __align__(128) h16 g_vnA2[Nn * 2 * Cc];
__device__ __align__(128) h16 g_vnB[Nn * Cc];
__device__ __align__(128) h16 g_attnA2[(size_t)Hh * Nn * 2 * Nn];
__device__ __align__(128) h16 g_xA2[Nn * 4 * Cc];        // trans_cls split: row [hi 2C | lo 2C]
__device__ __align__(128) h16 g_sim2A2[Nn * 2 * Nn];
__device__ __align__(128) h16 g_featB[2 * Cc * Nn];
__device__ __align__(128) h16 g_aveA2[Nn * 8 * Cc];      // row [hi 4C | lo 4C]
__device__ __align__(128) h16 g_W1B[2 * Cc * 2 * Cc];
__device__ __align__(128) h16 g_W2B[Cc * 4 * Cc];

// ---------------- helpers ----------------
__device__ __forceinline__ float warpMax(float v) {
#pragma unroll
    for (int o = 16; o; o >>= 1) v = fmaxf(v, __shfl_xor_sync(0xffffffffu, v, o));
    return v;
}
__device__ __forceinline__ float warpSum(float v) {
#pragma unroll
    for (int o = 16; o; o >>= 1) v += __shfl_xor_sync(0xffffffffu, v, o);
    return v;
}
__device__ float blockMax(float v, float* s) {
    int w = threadIdx.x >> 5, l = threadIdx.x & 31;
    v = warpMax(v);
    if (l == 0) s[w] = v;
    __syncthreads();
    float r = (l < 8) ? s[l] : -3.0e38f;
    r = warpMax(r);
    r = __shfl_sync(0xffffffffu, r, 0);
    __syncthreads();
    return r;
}
__device__ float blockSum(float v, float* s) {
    int w = threadIdx.x >> 5, l = threadIdx.x & 31;
    v = warpSum(v);
    if (l == 0) s[w] = v;
    __syncthreads();
    float r = (l < 8) ? s[l] : 0.0f;
    r = warpSum(r);
    r = __shfl_sync(0xffffffffu, r, 0);
    __syncthreads();
    return r;
}
__device__ __forceinline__ void splith(float x, h16& h, h16& l) {
    h = __float2half_rn(x);
    l = __float2half_rn(x - __half2float(h));
}
__device__ __forceinline__ uint32_t smem_u32(const void* p) {
    uint32_t a;
    asm("{ .reg .u64 t; cvta.to.shared.u64 t, %1; cvt.u32.u64 %0, t; }" : "=r"(a) : "l"(p));
    return a;
}
__device__ __forceinline__ void cp16(uint32_t s, const void* g) {
    asm volatile("cp.async.cg.shared.global [%0], [%1], 16;" :: "r"(s), "l"(g) : "memory");
}
__device__ __forceinline__ uint32_t swz(uint32_t off) {
    return off ^ ((off >> 3) & 0x70);
}
__device__ __forceinline__ void ldsm4(uint32_t* r, uint32_t a) {
    asm volatile("ldmatrix.sync.aligned.m8n8.x4.shared.b16 {%0,%1,%2,%3}, [%4];"
                 : "=r"(r[0]), "=r"(r[1]), "=r"(r[2]), "=r"(r[3]) : "r"(a));
}
__device__ __forceinline__ void mma16816(float* c, const uint32_t* a, uint32_t b0, uint32_t b1) {
    asm volatile(
        "mma.sync.aligned.m16n8k16.row.col.f32.f16.f16.f32 "
        "{%0,%1,%2,%3},{%4,%5,%6,%7},{%8,%9},{%0,%1,%2,%3};"
        : "+f"(c[0]), "+f"(c[1]), "+f"(c[2]), "+f"(c[3])
        : "r"(a[0]), "r"(a[1]), "r"(a[2]), "r"(a[3]), "r"(b0), "r"(b1));
}

// ---------------- HMMA GEMM: C[128x128] = (A_hi + A_lo)[M,K] * B[N,K]^T ----------------
// A rows: [hi K | lo K] (stride 2K). Outputs: fp32 C (optional), split-h16 Ch (optional,
// hi at r*2*ldch+col, lo at r*2*ldch+ldch+col). K % 64 == 0, K >= 128.
#define STAGE_B 49152
#define GSMEM (2 * STAGE_B)

__global__ void __launch_bounds__(256, 2) gemm_mma(
    const h16* __restrict__ A, const h16* __restrict__ B,
    float* __restrict__ C, h16* __restrict__ Ch,
    const float* __restrict__ bias, int K, int ldc, int ldch,
    long long sA, long long sB, long long sC, long long sCh)
{
    extern __shared__ char smem[];
    const uint32_t sbase = smem_u32(smem);
    const int t = threadIdx.x, lane = t & 31, wid = t >> 5;
    const int wm = (wid & 3) * 32, wn = (wid >> 2) * 64;

    A += (long long)blockIdx.z * sA;
    B += (long long)blockIdx.z * sB;
    if (C)  C  += (long long)blockIdx.z * sC;
    if (Ch) Ch += (long long)blockIdx.z * sCh;
    const int m0 = blockIdx.y * 128, n0 = blockIdx.x * 128;

    const uint32_t ahB[2] = {sbase,         sbase + STAGE_B};
    const uint32_t alB[2] = {sbase + 16384, sbase + STAGE_B + 16384};
    const uint32_t bB[2]  = {sbase + 32768, sbase + STAGE_B + 32768};

    uint32_t ld_sw[4];
#pragma unroll
    for (int s = 0; s < 4; s++) {
        uint32_t off = (uint32_t)(t >> 1) * 128 + (uint32_t)(t & 1) * 64 + s * 16;
        ld_sw[s] = swz(off);
    }
    const h16* Agh = A + (long long)(m0 + (t >> 1)) * 2 * K + (t & 1) * 32;
    const h16* Agl = Agh + K;
    const h16* Bg  = B + (long long)(n0 + (t >> 1)) * K + (t & 1) * 32;

    auto LOAD = [&](int st, int ch) {
#pragma unroll
        for (int s = 0; s < 4; s++) {
            cp16(ahB[st] + ld_sw[s], Agh + ch * 64 + s * 8);
            cp16(alB[st] + ld_sw[s], Agl + ch * 64 + s * 8);
            cp16(bB[st]  + ld_sw[s], Bg  + ch * 64 + s * 8);
        }
        asm volatile("cp.async.commit_group;" ::: "memory");
    };

    const uint32_t frow = (lane & 7) + ((lane >> 3) & 1) * 8;
    const uint32_t fbyte = (lane >> 4) * 16;

    float acc[2][8][4];
#pragma unroll
    for (int i = 0; i < 2; i++)
#pragma unroll
        for (int j = 0; j < 8; j++)
#pragma unroll
            for (int q = 0; q < 4; q++) acc[i][j][q] = 0.0f;

    const int nch = K >> 6;
    LOAD(0, 0);
    LOAD(1, 1);

    for (int c = 0; c < nch; ++c) {
        const int st = c & 1;
        asm volatile("cp.async.wait_group 1;" ::: "memory");
        __syncthreads();
#pragma unroll
        for (int ks = 0; ks < 4; ks++) {
            uint32_t bf[4][4], af[2][4];
#pragma unroll
            for (int jn = 0; jn < 4; jn++)
                ldsm4(bf[jn], bB[st] + swz((wn + jn * 16 + frow) * 128 + ks * 32 + fbyte));
            // hi pass
#pragma unroll
            for (int i = 0; i < 2; i++)
                ldsm4(af[i], ahB[st] + swz((wm + i * 16 + frow) * 128 + ks * 32 + fbyte));
#pragma unroll
            for (int i = 0; i < 2; i++)
#pragma unroll
                for (int j = 0; j < 8; j++) {
                    const int jn = j >> 1, sel = j & 1;
                    mma16816(acc[i][j], af[i], bf[jn][sel], bf[jn][sel + 2]);
                }
            // lo pass (same B frags)
#pragma unroll
            for (int i = 0; i < 2; i++)
                ldsm4(af[i], alB[st] + swz((wm + i * 16 + frow) * 128 + ks * 32 + fbyte));
#pragma unroll
            for (int i = 0; i < 2; i++)
#pragma unroll
                for (int j = 0; j < 8; j++) {
                    const int jn = j >> 1, sel = j & 1;
                    mma16816(acc[i][j], af[i], bf[jn][sel], bf[jn][sel + 2]);
                }
        }
        __syncthreads();
        if (c + 2 < nch) LOAD(st, c + 2);
    }

    // epilogue
    const int g = lane >> 2, tc = (lane & 3) * 2;
#pragma unroll
    for (int i = 0; i < 2; i++) {
        const int r0 = m0 + wm + i * 16 + g;
#pragma unroll
        for (int j = 0; j < 8; j++) {
            const int col = n0 + wn + j * 8 + tc;
            float bx = 0.0f, by = 0.0f;
            if (bias) { bx = bias[col]; by = bias[col + 1]; }
            float v00 = acc[i][j][0] + bx, v01 = acc[i][j][1] + by;
            float v10 = acc[i][j][2] + bx, v11 = acc[i][j][3] + by;
            if (C) {
                *(float2*)(C + (long long)r0 * ldc + col) = make_float2(v00, v01);
                *(float2*)(C + (long long)(r0 + 8) * ldc + col) = make_float2(v10, v11);
            }
            if (Ch) {
                h16 h0, l0, h1, l1;
                splith(v00, h0, l0); splith(v01, h1, l1);
                *(__half2*)(Ch + (long long)r0 * 2 * ldch + col) = __halves2half2(h0, h1);
                *(__half2*)(Ch + (long long)r0 * 2 * ldch + ldch + col) = __halves2half2(l0, l1);
                splith(v10, h0, l0); splith(v11, h1, l1);
                *(__half2*)(Ch + (long long)(r0 + 8) * 2 * ldch + col) = __halves2half2(h0, h1);
                *(__half2*)(Ch + (long long)(r0 + 8) * 2 * ldch + ldch + col) = __halves2half2(l0, l1);
            }
        }
    }
}

// ---------------- converts ----------------
// A-split: row -> [hi | lo]
__global__ void cvtA(const float* __restrict__ src, h16* __restrict__ dst, int K, int lda) {
    const size_t r = blockIdx.x;
    for (int j = threadIdx.x; j < K; j += blockDim.x) {
        h16 h, l;
        splith(src[r * lda + j], h, l);
        h16* d = dst + r * 2 * K + j;
        d[0] = h; d[K] = l;
    }
}
// plain fp16
__global__ void cvtB(const float* __restrict__ src, h16* __restrict__ dst, int K, int lda) {
    const size_t r = blockIdx.x;
    for (int j = threadIdx.x; j < K; j += blockDim.x)
        dst[r * K + j] = __float2half_rn(src[r * lda + j]);
}
// transpose to plain fp16: src [R x Cl](lda) -> dst [Cl x R]
__global__ void cvtBT(const float* __restrict__ src, h16* __restrict__ dst,
                      int R, int Cl, int lda, long long sSrc, long long sDst) {
    src += (long long)blockIdx.z * sSrc;
    dst += (long long)blockIdx.z * sDst;
    __shared__ float tile[32][33];
    const int c0 = blockIdx.x * 32, r0 = blockIdx.y * 32;
    const int tx = threadIdx.x, ty = threadIdx.y;
#pragma unroll
    for (int i = 0; i < 32; i += 8)
        tile[ty + i][tx] = src[(long long)(r0 + ty + i) * lda + c0 + tx];
    __syncthreads();
#pragma unroll
    for (int i = 0; i < 32; i += 8) {
        const int c = c0 + ty + i, r = r0 + tx;
        dst[(long long)c * R + r] = __float2half_rn(tile[tx][ty + i]);
    }
}

// ---------------- split + normalize + fold scales ----------------
__global__ void split_normalize(const float* __restrict__ cls_score,
                                const float* __restrict__ fg_score) {
    const int n = blockIdx.x, h = blockIdx.y, j = threadIdx.x;
    const float* bc = g_qkv_cls + (size_t)n * 3 * Cc + h * Dd + j;
    const float* br = g_qkv_reg + (size_t)n * 3 * Cc + h * Dd + j;
    float qc = bc[0], kc = bc[Cc], vv = bc[2 * Cc];
    float qr = br[0], kr = br[Cc];

    float sq[5] = {qc * qc, kc * kc, vv * vv, qr * qr, kr * kr};
    __shared__ float red[5][4];
    const int lane = j & 31, warp = j >> 5;
#pragma unroll
    for (int i = 0; i < 5; i++) {
        float v = warpSum(sq[i]);
        if (lane == 0) red[i][warp] = v;
    }
    __syncthreads();
    float inv[5];
#pragma unroll
    for (int i = 0; i < 5; i++)
        inv[i] = 1.0f / sqrtf(red[i][0] + red[i][1] + red[i][2] + red[i][3]);

    const float sc_c = SCALE_F * cls_score[n];
    const float sc_f = SCALE_F * fg_score[n];
    h16 h0, l0;

    const size_t qb0 = ((size_t)h * Nn + n) * 256;
    const size_t qb1 = ((size_t)(Hh + h) * Nn + n) * 256;
    splith(qc * inv[0], h0, l0);
    g_qnA2[qb0 + j] = h0; g_qnA2[qb0 + 128 + j] = l0;
    g_knB[((size_t)h * Nn + n) * Dd + j] = __float2half_rn(kc * inv[1] * sc_c);
    splith(qr * inv[3], h0, l0);
    g_qnA2[qb1 + j] = h0; g_qnA2[qb1 + 128 + j] = l0;
    g_knB[((size_t)(Hh + h) * Nn + n) * Dd + j] = __float2half_rn(kr * inv[4] * sc_f);

    g_v[((size_t)h * Nn + n) * Dd + j] = vv;

    // x_ori -> xA2 cols [C .. 2C), split form (row stride 4096, lo plane +2048)
    splith(vv, h0, l0);
    g_xA2[(size_t)n * 4096 + Cc + h * Dd + j] = h0;
    g_xA2[(size_t)n * 4096 + 2048 + Cc + h * Dd + j] = l0;

    const size_t vb = (size_t)n * 2048 + h * Dd + j;
    splith(vv * inv[2], h0, l0);
    g_vnA2[vb] = h0; g_vnA2[vb + 1024] = l0;
    g_vnB[(size_t)n * Cc + h * Dd + j] = h0;
}

// ---------------- dual softmax + combine + head-sum; attn as A-split fp16 ----------------
__global__ void __launch_bounds__(256) softmax_combine() {
    const int n = blockIdx.x, t = threadIdx.x;
    __shared__ float sc[Nn], sr[Nn], acc[Nn], red[8];
    for (int m = t; m < Nn; m += 256) acc[m] = 0.0f;
    for (int h = 0; h < Hh; h++) {
        const size_t base = ((size_t)h * Nn + n) * Nn;
        float lmc = -3.0e38f, lmr = -3.0e38f;
        for (int m = t; m < Nn; m += 256) {
            float a = g_S0[base + m], b = g_S1[base + m];
            sc[m] = a; sr[m] = b;
            lmc = fmaxf(lmc, a);
            lmr = fmaxf(lmr, b);
        }
        const float mc = blockMax(lmc, red), mr = blockMax(lmr, red);
        float lsc = 0.0f, lsr = 0.0f;
        for (int m = t; m < Nn; m += 256) {
            float ec = expf(sc[m] - mc), er = expf(sr[m] - mr);
            sc[m] = ec; sr[m] = er;
            lsc += ec; lsr += er;
        }
        const float ic = 0.5f / blockSum(lsc, red);
        const float ir = 0.5f / blockSum(lsr, red);
        h16* ab = g_attnA2 + ((size_t)h * Nn + n) * 2 * Nn;
        for (int m = t; m < Nn; m += 256) {
            float p = sc[m] * ic + sr[m] * ir;
            acc[m] += p;
            h16 hh, ll;
            splith(p, hh, ll);
            ab[m] = hh; ab[Nn + m] = ll;
        }
        __syncthreads();
    }
    for (int m = t; m < Nn; m += 256) g_attnsum[(size_t)n * Nn + m] = acc[m];
}

// ---------------- mask + softmax2 + renorm; sim2 as A-split fp16 ----------------
__global__ void __launch_bounds__(256) mask_softmax2() {
    const int n = blockIdx.x, t = threadIdx.x;
    __shared__ float buf[Nn], red[8];
    float lm = -3.0e38f;
    for (int m = t; m < Nn; m += 256) {
        float v = g_attnsum[(size_t)n * Nn + m] * 0.125f;
        buf[m] = v;
        lm = fmaxf(lm, v);
    }
    const float mx = blockMax(lm, red);
    float ls = 0.0f;
    for (int m = t; m < Nn; m += 256) {
        float e = expf(buf[m] - mx);
        buf[m] = e;
        ls += e;
    }
    const float inv = 1.0f / blockSum(ls, red);
    float lms = 0.0f;
    for (int m = t; m < Nn; m += 256) {
        float p = buf[m] * inv;
        float keep = (g_simraw[(size_t)n * Nn + m] > 6.0f) ? p : 0.0f;
        buf[m] = keep;
        lms += keep;
    }
    const float invm = 1.0f / blockSum(lms, red);
    h16* sb = g_sim2A2 + (size_t)n * 2 * Nn;
    for (int m = t; m < Nn; m += 256) {
        h16 hh, ll;
        splith(buf[m] * invm, hh, ll);
        sb[m] = hh; sb[Nn + m] = ll;
    }
}

// ---------------- launch ----------------
extern "C" void kernel_launch(void* const* d_in, const int* in_sizes, int n_in,
                              void* d_out, int out_size)
{
    const float* x_cls     = (const float*)d_in[0];
    const float* x_reg     = (const float*)d_in[1];
    const float* cls_score = (const float*)d_in[2];
    const float* fg_score  = (const float*)d_in[3];
    const float* W_qkv_cls = (const float*)d_in[4];
    const float* W_qkv_reg = (const float*)d_in[5];
    const float* W1        = (const float*)d_in[6];
    const float* b1        = (const float*)d_in[7];
    const float* W2        = (const float*)d_in[8];
    const float* b2        = (const float*)d_in[9];
    float* out = (float*)d_out;

    cudaFuncSetAttribute(gemm_mma, cudaFuncAttributeMaxDynamicSharedMemorySize, GSMEM);

#define ADDR(sym, var) float* var; cudaGetSymbolAddress((void**)&var, sym)
    ADDR(g_qkv_cls, qkvc); ADDR(g_qkv_reg, qkvr); ADDR(g_v, vraw);
    ADDR(g_S0, S0); ADDR(g_S1, S1); ADDR(g_simraw, simraw); ADDR(g_feat, feat);
#undef ADDR
#define HADDR(sym, var) h16* var; cudaGetSymbolAddress((void**)&var, sym)
    HADDR(g_xclsA2, xclsA2); HADDR(g_xregA2, xregA2);
    HADDR(g_WqcB, WqcB); HADDR(g_WqrB, WqrB);
    HADDR(g_qnA2, qnA2); HADDR(g_knB, knB); HADDR(g_vT, vT);
    HADDR(g_vnA2, vnA2); HADDR(g_vnB, vnB); HADDR(g_attnA2, attnA2);
    HADDR(g_xA2, xA2); HADDR(g_sim2A2, sim2A2); HADDR(g_featB, featB);
    HADDR(g_aveA2, aveA2); HADDR(g_W1B, W1B); HADDR(g_W2B, W2B);
#undef HADDR

    const long long NN = (long long)Nn * Nn;

    // converts
    cvtA<<<Nn, 256>>>(x_cls, xclsA2, Cc, Cc);
    cvtA<<<Nn, 256>>>(x_reg, xregA2, Cc, Cc);
    cvtB<<<3 * Cc, 256>>>(W_qkv_cls, WqcB, Cc, Cc);
    cvtB<<<3 * Cc, 256>>>(W_qkv_reg, WqrB, Cc, Cc);
    cvtB<<<2 * Cc, 256>>>(W1, W1B, 2 * Cc, 2 * Cc);
    cvtB<<<Cc, 256>>>(W2, W2B, 4 * Cc, 4 * Cc);

    // qkv projections (K = 1024)
    gemm_mma<<<dim3(24, 16, 1), 256, GSMEM>>>(xclsA2, WqcB, qkvc, nullptr, nullptr,
                                              Cc, 3 * Cc, 0, 0, 0, 0, 0);
    gemm_mma<<<dim3(24, 16, 1), 256, GSMEM>>>(xregA2, WqrB, qkvr, nullptr, nullptr,
                                              Cc, 3 * Cc, 0, 0, 0, 0, 0);

    split_normalize<<<dim3(Nn, Hh), 128>>>(cls_score, fg_score);
    cvtBT<<<dim3(4, 64, 8), dim3(32, 8)>>>(vraw, vT, Nn, Dd, Dd,
                                           (long long)Nn * Dd, (long long)Dd * Nn);

    // scores (K = 128 per head)
    gemm_mma<<<dim3(16, 16, 8), 256, GSMEM>>>(qnA2, knB, S0, nullptr, nullptr,
                                              Dd, Nn, 0, (long long)Nn * 256,
                                              (long long)Nn * Dd, NN, 0);
    gemm_mma<<<dim3(16, 16, 8), 256, GSMEM>>>(qnA2 + (size_t)Hh * Nn * 256,
                                              knB + (size_t)Hh * Nn * Dd,
                                              S1, nullptr, nullptr,
                                              Dd, Nn, 0, (long long)Nn * 256,
                                              (long long)Nn * Dd, NN, 0);
    // simraw (K = 1024)
    gemm_mma<<<dim3(16, 16, 1), 256, GSMEM>>>(vnA2, vnB, simraw, nullptr, nullptr,
                                              Cc, Nn, 0, 0, 0, 0, 0);

    softmax_combine<<<Nn, 256>>>();

    // x = attn @ v per head -> xA2 cols [0,C), split output only (K = 2048)
    gemm_mma<<<dim3(1, 16, 8), 256, GSMEM>>>(attnA2, vT, nullptr, xA2, nullptr,
                                             Nn, 0, 2 * Cc,
                                             (long long)Nn * 2 * Nn,
                                             (long long)Dd * Nn, 0, (long long)Dd);

    // feat = trans_cls @ W1^T + b1 -> g_feat fp32 AND aveA2 cols [2C,4C) (K = 2048)
    gemm_mma<<<dim3(16, 16, 1), 256, GSMEM>>>(xA2, W1B, feat, aveA2 + 2 * Cc, b1,
                                              2 * Cc, 2 * Cc, 4 * Cc, 0, 0, 0, 0);

    mask_softmax2<<<Nn, 256>>>();
    cvtBT<<<dim3(64, 64, 1), dim3(32, 8)>>>(feat, featB, Nn, 2 * Cc, 2 * Cc, 0, 0);

    // soft_sim = sim2 @ feat -> aveA2 cols [0,2C), split output only (K = 2048)
    gemm_mma<<<dim3(16, 16, 1), 256, GSMEM>>>(sim2A2, featB, nullptr, aveA2, nullptr,
                                              Nn, 0, 4 * Cc, 0, 0, 0, 0);

    // out = ave @ W2^T + b2 (K = 4096)
    gemm_mma<<<dim3(8, 16, 1), 256, GSMEM>>>(aveA2, W2B, out, nullptr, b2,
                                             4 * Cc, Cc, 0, 0, 0, 0, 0);
}